// round 2
// baseline (speedup 1.0000x reference)
#include <cuda_runtime.h>
#include <cuda_bf16.h>
#include <cstdint>

// Problem constants
#define B_  256
#define N_  131072
#define D_  256
#define TEMP_INV 20.0f   // 1 / 0.05

// GEMM tiling
#define KP      264          // smem row pitch in halfs (264*2 = 528 B = 33*16 -> 16B aligned rows, conflict-free ldmatrix)
#define NTILE   32           // cluster rows per chunk
#define NCHUNKS (N_ / NTILE) // 4096
#define SMEM_HALFS (B_ * KP + NTILE * KP)
#define SMEM_BYTES (SMEM_HALFS * 2)   // 135168 + 16896 = 152064 B

__device__ float g_rowsum[B_];
__device__ float g_tlogit[B_];

// ---------------------------------------------------------------------------
__global__ void init_kernel() {
    g_rowsum[threadIdx.x] = 0.0f;
}

// ---------------------------------------------------------------------------
// Exact fp32 target logits: one warp per batch row.
__global__ void tgt_kernel(const float* __restrict__ inputs,
                           const float* __restrict__ cluster,
                           const int* __restrict__ indexes,
                           const int* __restrict__ labels) {
    int gwarp = (blockIdx.x * blockDim.x + threadIdx.x) >> 5;
    if (gwarp >= B_) return;
    int lane = threadIdx.x & 31;
    int t = labels[indexes[gwarp]];
    const float* a = inputs + gwarp * D_;
    const float* b = cluster + (size_t)t * D_;
    float s = 0.0f;
#pragma unroll
    for (int k = lane; k < D_; k += 32) s = fmaf(a[k], b[k], s);
#pragma unroll
    for (int o = 16; o; o >>= 1) s += __shfl_xor_sync(0xffffffffu, s, o);
    if (lane == 0) g_tlogit[gwarp] = s * TEMP_INV;
}

// ---------------------------------------------------------------------------
__device__ __forceinline__ uint32_t s2u(const void* p) {
    return (uint32_t)__cvta_generic_to_shared(p);
}

__device__ __forceinline__ void ldsm4(uint32_t* r, uint32_t a) {
    asm volatile("ldmatrix.sync.aligned.m8n8.x4.shared.b16 {%0,%1,%2,%3}, [%4];"
                 : "=r"(r[0]), "=r"(r[1]), "=r"(r[2]), "=r"(r[3]) : "r"(a));
}

__device__ __forceinline__ void mma_bf16(float* c, const uint32_t* a,
                                         uint32_t b0, uint32_t b1) {
    asm volatile(
        "mma.sync.aligned.m16n8k16.row.col.f32.bf16.bf16.f32 "
        "{%0,%1,%2,%3}, {%4,%5,%6,%7}, {%8,%9}, {%0,%1,%2,%3};"
        : "+f"(c[0]), "+f"(c[1]), "+f"(c[2]), "+f"(c[3])
        : "r"(a[0]), "r"(a[1]), "r"(a[2]), "r"(a[3]), "r"(b0), "r"(b1));
}

__device__ __forceinline__ uint32_t f2bf2(float lo, float hi) {
    uint32_t r;
    asm("{ .reg .b16 l, h;\n\t"
        "  cvt.rn.bf16.f32 l, %1;\n\t"
        "  cvt.rn.bf16.f32 h, %2;\n\t"
        "  mov.b32 %0, {l, h}; }"
        : "=r"(r) : "f"(lo), "f"(hi));
    return r;
}

// Persistent fused GEMM + exp row-sum kernel.
// 8 warps: warp grid 4(M) x 2(N). M covered fully (256), per-chunk N = 32.
__global__ void __launch_bounds__(256, 1)
gemm_kernel(const float* __restrict__ inputs, const float* __restrict__ cluster) {
    extern __shared__ __nv_bfloat16 smem[];
    __nv_bfloat16* As = smem;            // [256][KP]
    __nv_bfloat16* Bs = smem + B_ * KP;  // [32][KP]

    const int tid  = threadIdx.x;
    const int lane = tid & 31;
    const int warp = tid >> 5;
    const int wm   = warp & 3;      // 0..3  -> m0 = wm*64
    const int wn   = warp >> 2;     // 0..1  -> n_off = wn*16
    const int m0   = wm * 64;
    const int n_off = wn * 16;

    // ---- Convert A (inputs fp32) -> bf16 smem, coalesced ----
    {
        const float4* in4 = (const float4*)inputs;
#pragma unroll
        for (int i = 0; i < (B_ * D_ / 4) / 256; i++) {   // 64 iters
            int g   = tid + i * 256;
            int row = g >> 6;       // 64 float4 per row
            int c4  = g & 63;
            float4 v = in4[g];
            uint2 u;
            u.x = f2bf2(v.x, v.y);
            u.y = f2bf2(v.z, v.w);
            *(uint2*)(As + row * KP + c4 * 4) = u;
        }
    }

    // ---- ldmatrix lane-address bases ----
    uint32_t aAddr[4];
#pragma unroll
    for (int mi = 0; mi < 4; mi++) {
        int arow = m0 + mi * 16 + (lane & 15);
        int acol = (lane >> 4) * 8;
        aAddr[mi] = s2u(As + arow * KP + acol);
    }
    uint32_t bAddr;
    {
        int brow = n_off + (lane & 7) + ((lane >> 4) << 3);
        int bcol = ((lane >> 3) & 1) * 8;
        bAddr = s2u(Bs + brow * KP + bcol);
    }

    float sum0[4] = {0.f, 0.f, 0.f, 0.f};   // rows m0+mi*16+(lane>>2)
    float sum1[4] = {0.f, 0.f, 0.f, 0.f};   // rows +8

    const float4* cf4 = (const float4*)cluster;
    const int stride = gridDim.x;
    int chunk = blockIdx.x;

    // Prefetch first chunk into registers (8 x float4 per thread = 32 KB/CTA)
    float4 stage[8];
    {
        int base = chunk * (NTILE * 64);   // float4 index
#pragma unroll
        for (int j = 0; j < 8; j++) stage[j] = cf4[base + tid + j * 256];
    }
    __syncthreads();   // A ready in smem

    while (chunk < NCHUNKS) {
        // ---- store staged B chunk (fp32 regs -> bf16 smem) ----
#pragma unroll
        for (int j = 0; j < 8; j++) {
            int g   = tid + j * 256;
            int row = g >> 6;
            int c4  = g & 63;
            float4 v = stage[j];
            uint2 u;
            u.x = f2bf2(v.x, v.y);
            u.y = f2bf2(v.z, v.w);
            *(uint2*)(Bs + row * KP + c4 * 4) = u;
        }
        __syncthreads();

        // ---- prefetch next chunk while computing this one ----
        int nxt = chunk + stride;
        if (nxt < NCHUNKS) {
            int base = nxt * (NTILE * 64);
#pragma unroll
            for (int j = 0; j < 8; j++) stage[j] = cf4[base + tid + j * 256];
        }

        // ---- mma mainloop: M=256(4 warps x 64), N=32(2 warps x 16), K=256 ----
        float acc[4][2][4];
#pragma unroll
        for (int mi = 0; mi < 4; mi++)
#pragma unroll
            for (int ni = 0; ni < 2; ni++)
#pragma unroll
                for (int e = 0; e < 4; e++) acc[mi][ni][e] = 0.0f;

#pragma unroll
        for (int kk = 0; kk < 16; kk++) {
            uint32_t a[4][4], b[4];
#pragma unroll
            for (int mi = 0; mi < 4; mi++) ldsm4(a[mi], aAddr[mi] + kk * 32);
            ldsm4(b, bAddr + kk * 32);
#pragma unroll
            for (int mi = 0; mi < 4; mi++) {
                mma_bf16(acc[mi][0], a[mi], b[0], b[1]);
                mma_bf16(acc[mi][1], a[mi], b[2], b[3]);
            }
        }

        // ---- epilogue: exp and accumulate per-thread row partials ----
#pragma unroll
        for (int mi = 0; mi < 4; mi++) {
            float s0 = 0.f, s1 = 0.f;
#pragma unroll
            for (int ni = 0; ni < 2; ni++) {
                s0 += __expf(acc[mi][ni][0] * TEMP_INV) + __expf(acc[mi][ni][1] * TEMP_INV);
                s1 += __expf(acc[mi][ni][2] * TEMP_INV) + __expf(acc[mi][ni][3] * TEMP_INV);
            }
            sum0[mi] += s0;
            sum1[mi] += s1;
        }

        __syncthreads();   // protect Bs before next overwrite
        chunk = nxt;
    }

    // ---- reduce quad (lanes sharing a row) and atomically add once per warp ----
#pragma unroll
    for (int mi = 0; mi < 4; mi++) {
#pragma unroll
        for (int o = 1; o <= 2; o <<= 1) {
            sum0[mi] += __shfl_xor_sync(0xffffffffu, sum0[mi], o);
            sum1[mi] += __shfl_xor_sync(0xffffffffu, sum1[mi], o);
        }
        if ((lane & 3) == 0) {
            int r = m0 + mi * 16 + (lane >> 2);
            atomicAdd(&g_rowsum[r],     sum0[mi]);
            atomicAdd(&g_rowsum[r + 8], sum1[mi]);
        }
    }
}

// ---------------------------------------------------------------------------
__global__ void fin_kernel(float* __restrict__ out) {
    __shared__ float red[B_];
    int i = threadIdx.x;
    float S = g_rowsum[i];
    float p = expf(g_tlogit[i]) / (S + 1e-6f);
    red[i] = -logf(p + 1e-6f);
    __syncthreads();
#pragma unroll
    for (int s = 128; s > 0; s >>= 1) {
        if (i < s) red[i] += red[i + s];
        __syncthreads();
    }
    if (i == 0) out[0] = red[0] * (1.0f / (float)B_);
}

// ---------------------------------------------------------------------------
extern "C" void kernel_launch(void* const* d_in, const int* in_sizes, int n_in,
                              void* d_out, int out_size) {
    const float* inputs  = (const float*)d_in[0];
    const float* cluster = (const float*)d_in[1];
    // d_in[2] = instance_features : unused by the loss
    const int* indexes = (const int*)d_in[3];
    const int* labels  = (const int*)d_in[4];
    float* out = (float*)d_out;

    int sms = 0;
    cudaDeviceGetAttribute(&sms, cudaDevAttrMultiProcessorCount, 0);
    if (sms <= 0) sms = 148;
    if (sms > NCHUNKS) sms = NCHUNKS;

    cudaFuncSetAttribute(gemm_kernel,
                         cudaFuncAttributeMaxDynamicSharedMemorySize, SMEM_BYTES);

    init_kernel<<<1, B_>>>();
    tgt_kernel<<<(B_ * 32 + 1023) / 1024, 1024>>>(inputs, cluster, indexes, labels);
    gemm_kernel<<<sms, 256, SMEM_BYTES>>>(inputs, cluster);
    fin_kernel<<<1, B_>>>(out);
}

// round 5
// speedup vs baseline: 1.1786x; 1.1786x over previous
#include <cuda_runtime.h>
#include <cuda_bf16.h>
#include <cstdint>

// ---------------------------------------------------------------------------
// Problem constants
#define B_       256
#define N_       131072
#define D_       256
#define TEMP_INV 20.0f        // 1 / 0.05

// GEMM tiling
#define KP      264           // smem row pitch in halfs (528 B = 33*16 -> 16B-aligned, conflict-free ldmatrix)
#define NTILE   64            // cluster rows per chunk
#define NCHUNKS (N_ / NTILE)  // 2048

// Shared memory (halfs): A[256][KP], B0[64][KP], B1[64][KP]
#define SMEM_HALFS (B_ * KP + 2 * NTILE * KP)
#define SMEM_BYTES (SMEM_HALFS * 2)          // 135168 + 67584 = 202752 B

#define MAXCTA 256
__device__ float g_partial[MAXCTA * B_];     // per-CTA partial row sums of exp(logits)

// ---------------------------------------------------------------------------
__device__ __forceinline__ uint32_t s2u(const void* p) {
    return (uint32_t)__cvta_generic_to_shared(p);
}

__device__ __forceinline__ void ldsm4(uint32_t* r, uint32_t a) {
    asm volatile("ldmatrix.sync.aligned.m8n8.x4.shared.b16 {%0,%1,%2,%3}, [%4];"
                 : "=r"(r[0]), "=r"(r[1]), "=r"(r[2]), "=r"(r[3]) : "r"(a));
}

__device__ __forceinline__ void mma_bf16(float* c, const uint32_t* a,
                                         uint32_t b0, uint32_t b1) {
    asm volatile(
        "mma.sync.aligned.m16n8k16.row.col.f32.bf16.bf16.f32 "
        "{%0,%1,%2,%3}, {%4,%5,%6,%7}, {%8,%9}, {%0,%1,%2,%3};"
        : "+f"(c[0]), "+f"(c[1]), "+f"(c[2]), "+f"(c[3])
        : "r"(a[0]), "r"(a[1]), "r"(a[2]), "r"(a[3]), "r"(b0), "r"(b1));
}

__device__ __forceinline__ uint32_t f2bf2(float lo, float hi) {
    uint32_t r;
    asm("{ .reg .b16 l, h;\n\t"
        "  cvt.rn.bf16.f32 l, %1;\n\t"
        "  cvt.rn.bf16.f32 h, %2;\n\t"
        "  mov.b32 %0, {l, h}; }"
        : "=r"(r) : "f"(lo), "f"(hi));
    return r;
}

// ---------------------------------------------------------------------------
// Persistent fused GEMM + exp + row-sum kernel (mma.sync path).
// 8 warps, warp grid 4(M) x 2(N): warp M=64 rows, warp N=32 cols per chunk.
// B double-buffered in smem; next chunk register-prefetched during mma.
__global__ void __launch_bounds__(256, 1)
gemm_kernel(const float* __restrict__ inputs, const float* __restrict__ cluster) {
    extern __shared__ __nv_bfloat16 smem[];
    __nv_bfloat16* As  = smem;                       // [256][KP]
    __nv_bfloat16* Bs0 = smem + B_ * KP;             // [64][KP]
    __nv_bfloat16* Bs1 = Bs0 + NTILE * KP;           // [64][KP]

    const int tid   = threadIdx.x;
    const int lane  = tid & 31;
    const int warp  = tid >> 5;
    const int wm    = warp & 3;       // m0 = wm*64
    const int wn    = warp >> 2;      // n_off = wn*32
    const int m0    = wm * 64;
    const int n_off = wn * 32;
    const int grid  = gridDim.x;

    // ---- Convert A (inputs fp32 [256][256]) -> bf16 smem, coalesced ----
    {
        const float4* in4 = (const float4*)inputs;
#pragma unroll
        for (int i = 0; i < 64; i++) {               // 16384 float4 / 256 thr
            int g   = tid + i * 256;
            int row = g >> 6;
            int c4  = g & 63;
            float4 v = in4[g];
            uint2 u; u.x = f2bf2(v.x, v.y); u.y = f2bf2(v.z, v.w);
            *(uint2*)(As + row * KP + c4 * 4) = u;
        }
    }

    // ---- ldmatrix lane-address bases ----
    uint32_t aAddr[4];
#pragma unroll
    for (int mi = 0; mi < 4; mi++) {
        int arow = m0 + mi * 16 + (lane & 15);
        int acol = (lane >> 4) * 8;
        aAddr[mi] = s2u(As + arow * KP + acol);
    }
    // B base within a buffer (add buffer offset at use): two n16 groups (bp=0,1)
    uint32_t bOff[2];
    {
        int brow = n_off + (lane & 7) + ((lane >> 4) << 3);
        int bcol = ((lane >> 3) & 1) * 8;
        bOff[0] = (uint32_t)((brow * KP + bcol) * 2);
        bOff[1] = bOff[0] + 16 * KP * 2;
    }
    const uint32_t b0u = s2u(Bs0), b1u = s2u(Bs1);

    float sum0[4] = {0.f, 0.f, 0.f, 0.f};   // rows m0+mi*16+(lane>>2)
    float sum1[4] = {0.f, 0.f, 0.f, 0.f};   // rows +8

    // ---- register-stage first B chunk (64 rows x 64 float4 = 4096 f4) ----
    const float4* cf4 = (const float4*)cluster;
    int c = blockIdx.x;
    float4 stage[16];
    {
        long base = (long)c * (NTILE * 64);
#pragma unroll
        for (int t = 0; t < 16; t++) stage[t] = cf4[base + tid + t * 256];
    }
    __syncthreads();   // A visible

    int j = 0;
    for (; c < NCHUNKS; c += grid, j++) {
        const int p = j & 1;
        __nv_bfloat16* Bw = p ? Bs1 : Bs0;
        const uint32_t bBase = p ? b1u : b0u;

        // ---- store staged B chunk (fp32 regs -> bf16 smem buffer p) ----
#pragma unroll
        for (int t = 0; t < 16; t++) {
            int g   = tid + t * 256;
            int row = g >> 6;                        // 0..63
            int c4  = g & 63;
            float4 v = stage[t];
            uint2 u; u.x = f2bf2(v.x, v.y); u.y = f2bf2(v.z, v.w);
            *(uint2*)(Bw + row * KP + c4 * 4) = u;
        }
        __syncthreads();   // B[p] visible to all warps; B[p^1] readers (iter j-1) done

        // ---- prefetch next chunk into registers (hidden under mma) ----
        if (c + grid < NCHUNKS) {
            long base = (long)(c + grid) * (NTILE * 64);
#pragma unroll
            for (int t = 0; t < 16; t++) stage[t] = cf4[base + tid + t * 256];
        }

        // ---- mma mainloop: warp tile M=64 x N=32, K=256 ----
        float acc[4][4][4];
#pragma unroll
        for (int mi = 0; mi < 4; mi++)
#pragma unroll
            for (int ni = 0; ni < 4; ni++)
#pragma unroll
                for (int e = 0; e < 4; e++) acc[mi][ni][e] = 0.0f;

#pragma unroll
        for (int kk = 0; kk < 16; kk++) {
            uint32_t a[4][4], b[2][4];
#pragma unroll
            for (int mi = 0; mi < 4; mi++) ldsm4(a[mi], aAddr[mi] + kk * 32);
#pragma unroll
            for (int bp = 0; bp < 2; bp++) ldsm4(b[bp], bBase + bOff[bp] + kk * 32);
#pragma unroll
            for (int mi = 0; mi < 4; mi++) {
#pragma unroll
                for (int bp = 0; bp < 2; bp++) {
                    mma_bf16(acc[mi][2 * bp + 0], a[mi], b[bp][0], b[bp][1]);
                    mma_bf16(acc[mi][2 * bp + 1], a[mi], b[bp][2], b[bp][3]);
                }
            }
        }

        // ---- epilogue: exp + accumulate per-thread row partials ----
#pragma unroll
        for (int mi = 0; mi < 4; mi++) {
            float s0 = 0.f, s1 = 0.f;
#pragma unroll
            for (int ni = 0; ni < 4; ni++) {
                s0 += __expf(acc[mi][ni][0] * TEMP_INV) + __expf(acc[mi][ni][1] * TEMP_INV);
                s1 += __expf(acc[mi][ni][2] * TEMP_INV) + __expf(acc[mi][ni][3] * TEMP_INV);
            }
            sum0[mi] += s0;
            sum1[mi] += s1;
        }
    }

    // ---- reduce: quad shfl -> smem cross-warp (wn pair) -> per-CTA write ----
    __syncthreads();                       // done with Bs; reuse as reduce buffer
    float* pbuf = (float*)Bs0;             // [2][256]
#pragma unroll
    for (int mi = 0; mi < 4; mi++) {
#pragma unroll
        for (int o = 1; o <= 2; o <<= 1) {
            sum0[mi] += __shfl_xor_sync(0xffffffffu, sum0[mi], o);
            sum1[mi] += __shfl_xor_sync(0xffffffffu, sum1[mi], o);
        }
        if ((lane & 3) == 0) {
            int r = m0 + mi * 16 + (lane >> 2);
            pbuf[wn * B_ + r]     = sum0[mi];
            pbuf[wn * B_ + r + 8] = sum1[mi];
        }
    }
    __syncthreads();
    if (tid < B_)
        g_partial[blockIdx.x * B_ + tid] = pbuf[tid] + pbuf[B_ + tid];
}

// ---------------------------------------------------------------------------
// Finalize: exact fp32 target logits (warp per row) + partial reduction + loss.
__global__ void __launch_bounds__(1024)
fin_kernel(const float* __restrict__ inputs, const float* __restrict__ cluster,
           const int* __restrict__ indexes, const int* __restrict__ labels,
           float* __restrict__ out, int ncta) {
    __shared__ float tl[B_];
    __shared__ float red[B_];
    const int tid  = threadIdx.x;
    const int lane = tid & 31;
    const int warp = tid >> 5;     // 32 warps

    for (int r = warp; r < B_; r += 32) {
        int t = labels[indexes[r]];
        const float* a = inputs + r * D_;
        const float* b = cluster + (size_t)t * D_;
        float s = 0.0f;
#pragma unroll
        for (int k = lane; k < D_; k += 32) s = fmaf(a[k], b[k], s);
#pragma unroll
        for (int o = 16; o; o >>= 1) s += __shfl_xor_sync(0xffffffffu, s, o);
        if (lane == 0) tl[r] = s * TEMP_INV;
    }
    __syncthreads();

    if (tid < B_) {
        float S = 0.0f;
        for (int ci = 0; ci < ncta; ci++) S += g_partial[ci * B_ + tid];
        float p = __expf(tl[tid]) / (S + 1e-6f);
        red[tid] = -logf(p + 1e-6f);
    }
    __syncthreads();
#pragma unroll
    for (int s = 128; s > 0; s >>= 1) {
        if (tid < s) red[tid] += red[tid + s];
        __syncthreads();
    }
    if (tid == 0) out[0] = red[0] * (1.0f / (float)B_);
}

// ---------------------------------------------------------------------------
extern "C" void kernel_launch(void* const* d_in, const int* in_sizes, int n_in,
                              void* d_out, int out_size) {
    const float* inputs  = (const float*)d_in[0];
    const float* cluster = (const float*)d_in[1];
    // d_in[2] = instance_features : unused by the loss
    const int* indexes = (const int*)d_in[3];
    const int* labels  = (const int*)d_in[4];
    float* out = (float*)d_out;

    int sms = 0;
    cudaDeviceGetAttribute(&sms, cudaDevAttrMultiProcessorCount, 0);
    if (sms <= 0) sms = 148;
    if (sms > MAXCTA) sms = MAXCTA;
    if (sms > NCHUNKS) sms = NCHUNKS;

    cudaFuncSetAttribute(gemm_kernel,
                         cudaFuncAttributeMaxDynamicSharedMemorySize, SMEM_BYTES);

    gemm_kernel<<<sms, 256, SMEM_BYTES>>>(inputs, cluster);
    fin_kernel<<<1, 1024>>>(inputs, cluster, indexes, labels, out, sms);
}